// round 16
// baseline (speedup 1.0000x reference)
#include <cuda_runtime.h>
#include <cuda_bf16.h>

// Batched EKF: predict (F x, F P F^T + Q) + update with H = [I3 | 0].
// Round 16: R15 (best bench: single-tile CTAs, grid=8192) + __launch_bounds__
// (64, 8) to cap regs at 128 -> 8 resident CTAs/SM (was 7 at 140 regs).

#define S_DIM 8
#define TPB 64

// P: 64 tracklets x 16 float4, XOR swizzle slot = bt*16 + (s ^ (bt & 7))
#define PSLOT(bt, s) (((bt) << 4) + ((s) ^ ((bt) & 7)))

// buffer float offsets
#define OFFB_P 0                          // 64*16*4 = 4096 floats
#define OFFB_X 4096                       // 64*8    = 512
#define OFFB_Z 4608                       // 64*3    = 192
#define BUF_FLOATS 4800                   // 19200 B

#define OFF_QU BUF_FLOATS                 // 4800
#define OFF_RU (OFF_QU + 64)              // 4864
#define SMEM_FLOATS (OFF_RU + 16)         // 4880
#define SMEM_BYTES  (SMEM_FLOATS * 4)     // 19520

__device__ __forceinline__ void cp16(void* dst, const void* src) {
    unsigned d = (unsigned)__cvta_generic_to_shared(dst);
    asm volatile("cp.async.cg.shared.global [%0], [%1], 16;" :: "r"(d), "l"(src));
}
__device__ __forceinline__ void cp_commit() {
    asm volatile("cp.async.commit_group;" ::: "memory");
}
template <int N>
__device__ __forceinline__ void cp_wait() {
    asm volatile("cp.async.wait_group %0;" :: "n"(N) : "memory");
}

__global__ __launch_bounds__(TPB, 8)
void ekf_kernel(const float* __restrict__ x_in,
                const float* __restrict__ P_in,
                const float* __restrict__ z_in,
                const float* __restrict__ Q_in,
                const float* __restrict__ R_in,
                float* __restrict__ out,
                int B)
{
    extern __shared__ float smem[];
    float* sQu = smem + OFF_QU;
    float* sRu = smem + OFF_RU;
    const int tid = threadIdx.x;

    const int tile = blockIdx.x;
    const int b0   = tile * TPB;

    float4* bP  = reinterpret_cast<float4*>(smem + OFFB_P);
    float4* bx  = reinterpret_cast<float4*>(smem + OFFB_X);
    float*  bz  = smem + OFFB_Z;

    // ---- prefetch this tile via cp.async (19.2KB in flight) ----
    {
        const float4* Pg = reinterpret_cast<const float4*>(P_in) + (size_t)b0 * 16;
        #pragma unroll
        for (int i = 0; i < 16; ++i) {
            int l = i * TPB + tid;
            cp16(&bP[PSLOT(l >> 4, l & 15)], &Pg[l]);
        }
        const float4* xg = reinterpret_cast<const float4*>(x_in) + (size_t)b0 * 2;
        #pragma unroll
        for (int i = 0; i < 2; ++i) {
            int l = i * TPB + tid;
            cp16(&bx[l], &xg[l]);
        }
        // z: identity staging (pitch 3) -> flat 768B bulk copy as 48 x 16B
        const float4* zg4 = reinterpret_cast<const float4*>(z_in + (size_t)b0 * 3);
        float4* bz4 = reinterpret_cast<float4*>(bz);
        if (tid < 48) cp16(&bz4[tid], &zg4[tid]);
    }
    cp_commit();

    // Q/R: broadcast tensors -> read tracklet 0's copy once (L2-resident)
    if (tid < 16) {
        reinterpret_cast<float4*>(sQu)[tid] =
            reinterpret_cast<const float4*>(Q_in)[tid];
    } else if (tid >= 32 && tid < 41) {
        sRu[tid - 32] = R_in[tid - 32];
    }

    cp_wait<0>();
    __syncthreads();

    const float dt  = 0.1f;
    const float dt2 = 0.005f;

    // ---- consume own slots into registers (swizzled, conflict-free) ----
    float P[64];
    #pragma unroll
    for (int i = 0; i < 16; ++i) {
        float4 v = bP[PSLOT(tid, i)];
        P[i * 4 + 0] = v.x; P[i * 4 + 1] = v.y;
        P[i * 4 + 2] = v.z; P[i * 4 + 3] = v.w;
    }
    float xv[8];
    {
        float4 a = bx[tid * 2 + 0], c = bx[tid * 2 + 1];
        xv[0] = a.x; xv[1] = a.y; xv[2] = a.z; xv[3] = a.w;
        xv[4] = c.x; xv[5] = c.y; xv[6] = c.z; xv[7] = c.w;
    }
    float z0 = bz[tid * 3 + 0];
    float z1 = bz[tid * 3 + 1];
    float z2 = bz[tid * 3 + 2];

    // ---- x_pred = F x ----
    const float xp0 = xv[0] + dt * xv[3] + dt2 * xv[6];
    const float xp1 = xv[1] + dt * xv[4] + dt2 * xv[7];
    const float xp2 = xv[2] + dt * xv[5];
    const float xp3 = xv[3] + dt * xv[6];
    const float xp4 = xv[4] + dt * xv[7];
    const float xp5 = xv[5];
    const float xp6 = xv[6];
    const float xp7 = xv[7];

    // ---- P <- F P ----
    #pragma unroll
    for (int j = 0; j < 8; ++j) {
        float r3 = P[3 * 8 + j], r4 = P[4 * 8 + j], r5 = P[5 * 8 + j];
        float r6 = P[6 * 8 + j], r7 = P[7 * 8 + j];
        P[0 * 8 + j] += dt * r3 + dt2 * r6;
        P[1 * 8 + j] += dt * r4 + dt2 * r7;
        P[2 * 8 + j] += dt * r5;
        P[3 * 8 + j] = r3 + dt * r6;
        P[4 * 8 + j] = r4 + dt * r7;
    }
    // ---- P <- (F P) F^T ----
    #pragma unroll
    for (int i = 0; i < 8; ++i) {
        float* row = &P[i * 8];
        float c3 = row[3], c4 = row[4], c5 = row[5], c6 = row[6], c7 = row[7];
        row[0] += dt * c3 + dt2 * c6;
        row[1] += dt * c4 + dt2 * c7;
        row[2] += dt * c5;
        row[3] = c3 + dt * c6;
        row[4] = c4 + dt * c7;
    }
    // ---- P += Q ----
    #pragma unroll
    for (int i = 0; i < 64; ++i) P[i] += sQu[i];

    // ---- S = P[0:3,0:3] + R ; adjugate inverse ----
    float S00 = P[0]  + sRu[0], S01 = P[1]  + sRu[1], S02 = P[2]  + sRu[2];
    float S10 = P[8]  + sRu[3], S11 = P[9]  + sRu[4], S12 = P[10] + sRu[5];
    float S20 = P[16] + sRu[6], S21 = P[17] + sRu[7], S22 = P[18] + sRu[8];

    float c00 = S11 * S22 - S12 * S21;
    float c01 = S12 * S20 - S10 * S22;
    float c02 = S10 * S21 - S11 * S20;
    float det = S00 * c00 + S01 * c01 + S02 * c02;
    float id  = 1.0f / det;

    float i00 = c00 * id;
    float i10 = c01 * id;
    float i20 = c02 * id;
    float i01 = (S02 * S21 - S01 * S22) * id;
    float i11 = (S00 * S22 - S02 * S20) * id;
    float i21 = (S01 * S20 - S00 * S21) * id;
    float i02 = (S01 * S12 - S02 * S11) * id;
    float i12 = (S02 * S10 - S00 * S12) * id;
    float i22 = (S00 * S11 - S01 * S10) * id;

    // ---- K = P[:,0:3] @ Sinv ----
    float K0[8], K1[8], K2[8];
    #pragma unroll
    for (int i = 0; i < 8; ++i) {
        float p0 = P[i * 8 + 0], p1 = P[i * 8 + 1], p2 = P[i * 8 + 2];
        K0[i] = p0 * i00 + p1 * i10 + p2 * i20;
        K1[i] = p0 * i01 + p1 * i11 + p2 * i21;
        K2[i] = p0 * i02 + p1 * i12 + p2 * i22;
    }

    // ---- innovation + x_upd ----
    float n0 = z0 - xp0;
    float n1 = z1 - xp1;
    float n2 = z2 - xp2;

    float xu[8];
    xu[0] = xp0 + K0[0] * n0 + K1[0] * n1 + K2[0] * n2;
    xu[1] = xp1 + K0[1] * n0 + K1[1] * n1 + K2[1] * n2;
    xu[2] = xp2 + K0[2] * n0 + K1[2] * n1 + K2[2] * n2;
    xu[3] = xp3 + K0[3] * n0 + K1[3] * n1 + K2[3] * n2;
    xu[4] = xp4 + K0[4] * n0 + K1[4] * n1 + K2[4] * n2;
    xu[5] = xp5 + K0[5] * n0 + K1[5] * n1 + K2[5] * n2;
    xu[6] = xp6 + K0[6] * n0 + K1[6] * n1 + K2[6] * n2;
    xu[7] = xp7 + K0[7] * n0 + K1[7] * n1 + K2[7] * n2;

    // ---- P_upd = P - K @ P[0:3,:]  (shadow arrays: max ILP epilogue) ----
    float HP0[8], HP1[8], HP2[8];
    #pragma unroll
    for (int j = 0; j < 8; ++j) {
        HP0[j] = P[0 * 8 + j];
        HP1[j] = P[1 * 8 + j];
        HP2[j] = P[2 * 8 + j];
    }
    #pragma unroll
    for (int i = 0; i < 8; ++i) {
        #pragma unroll
        for (int j = 0; j < 8; ++j) {
            P[i * 8 + j] -= K0[i] * HP0[j] + K1[i] * HP1[j] + K2[i] * HP2[j];
        }
    }

    // ---- stage outputs into own slots (overwrite consumed inputs) ----
    #pragma unroll
    for (int i = 0; i < 16; ++i) {
        bP[PSLOT(tid, i)] = make_float4(P[i * 4 + 0], P[i * 4 + 1],
                                        P[i * 4 + 2], P[i * 4 + 3]);
    }
    bx[tid * 2 + 0] = make_float4(xu[0], xu[1], xu[2], xu[3]);
    bx[tid * 2 + 1] = make_float4(xu[4], xu[5], xu[6], xu[7]);
    __syncthreads();

    // ---- coalesced streaming stores ----
    {
        float4* ox = reinterpret_cast<float4*>(out) + (size_t)b0 * 2;
        #pragma unroll
        for (int i = 0; i < 2; ++i) {
            int l = i * TPB + tid;
            __stcs(&ox[l], bx[l]);
        }
    }
    {
        float4* oP = reinterpret_cast<float4*>(out + (size_t)B * 8) + (size_t)b0 * 16;
        #pragma unroll
        for (int i = 0; i < 16; ++i) {
            int l = i * TPB + tid;
            __stcs(&oP[l], bP[PSLOT(l >> 4, l & 15)]);
        }
    }
}

extern "C" void kernel_launch(void* const* d_in, const int* in_sizes, int n_in,
                              void* d_out, int out_size)
{
    const float* x = (const float*)d_in[0];
    const float* P = (const float*)d_in[1];
    const float* z = (const float*)d_in[2];
    const float* Q = (const float*)d_in[3];
    const float* R = (const float*)d_in[4];
    float* out = (float*)d_out;

    const int B  = in_sizes[0] / S_DIM;        // x is [B, 8, 1]
    const int grid = B / TPB;                  // 8192 (B divisible by 64)

    static bool attr_set = false;              // idempotent host-side attribute
    if (!attr_set) {
        cudaFuncSetAttribute(ekf_kernel,
                             cudaFuncAttributeMaxDynamicSharedMemorySize, SMEM_BYTES);
        attr_set = true;
    }
    ekf_kernel<<<grid, TPB, SMEM_BYTES>>>(x, P, z, Q, R, out, B);
}

// round 17
// speedup vs baseline: 1.0006x; 1.0006x over previous
#include <cuda_runtime.h>
#include <cuda_bf16.h>

// Batched EKF: predict (F x, F P F^T + Q) + update with H = [I3 | 0].
// FINAL (session answer, = Round 15): single-tile CTAs, grid=8192, cp.async
// staging with XOR-swizzled P layout, broadcast Q/R loaded once per block,
// streaming stores. Converged at the mixed-R/W DRAM turnaround floor:
// 107us (first correct) -> 51.26us, ~5.5TB/s effective of 8TB/s spec.
//
// Techniques locked in across 16 rounds:
//  - traffic: Q/R are broadcast tensors -> read tracklet 0's copy only
//    (880 -> 588 B/tracklet, -33% DRAM)
//  - L1: all global access warp-coalesced via smem staging (R1's per-thread
//    256B blocks were L1tex-wavefront-bound at 82%)
//  - overlap: cp.async.cg global->smem keeps DRAM queues full through the
//    compute phase; smem slots reused for output staging
//  - layout: XOR swizzle (slot = bt*16 + (s ^ (bt&7))) is conflict-free for
//    both the coalesced fill and the per-thread 16-float4 drain
//  Falsified along the way: shuffle-based 8-thread/tracklet (SHFL is L1TEX),
//  persistent grids (straggler tail), 6+ CTAs/SM (no effect at the floor),
//  __stwt (writeback already overlapped).

#define S_DIM 8
#define TPB 64

// P: 64 tracklets x 16 float4, XOR swizzle slot = bt*16 + (s ^ (bt & 7))
#define PSLOT(bt, s) (((bt) << 4) + ((s) ^ ((bt) & 7)))

// buffer float offsets
#define OFFB_P 0                          // 64*16*4 = 4096 floats
#define OFFB_X 4096                       // 64*8    = 512
#define OFFB_Z 4608                       // 64*3    = 192
#define BUF_FLOATS 4800                   // 19200 B

#define OFF_QU BUF_FLOATS                 // 4800
#define OFF_RU (OFF_QU + 64)              // 4864
#define SMEM_FLOATS (OFF_RU + 16)         // 4880
#define SMEM_BYTES  (SMEM_FLOATS * 4)     // 19520

__device__ __forceinline__ void cp16(void* dst, const void* src) {
    unsigned d = (unsigned)__cvta_generic_to_shared(dst);
    asm volatile("cp.async.cg.shared.global [%0], [%1], 16;" :: "r"(d), "l"(src));
}
__device__ __forceinline__ void cp_commit() {
    asm volatile("cp.async.commit_group;" ::: "memory");
}
template <int N>
__device__ __forceinline__ void cp_wait() {
    asm volatile("cp.async.wait_group %0;" :: "n"(N) : "memory");
}

__global__ __launch_bounds__(TPB)
void ekf_kernel(const float* __restrict__ x_in,
                const float* __restrict__ P_in,
                const float* __restrict__ z_in,
                const float* __restrict__ Q_in,
                const float* __restrict__ R_in,
                float* __restrict__ out,
                int B)
{
    extern __shared__ float smem[];
    float* sQu = smem + OFF_QU;
    float* sRu = smem + OFF_RU;
    const int tid = threadIdx.x;

    const int tile = blockIdx.x;
    const int b0   = tile * TPB;

    float4* bP  = reinterpret_cast<float4*>(smem + OFFB_P);
    float4* bx  = reinterpret_cast<float4*>(smem + OFFB_X);
    float*  bz  = smem + OFFB_Z;

    // ---- prefetch this tile via cp.async (19.2KB in flight) ----
    {
        const float4* Pg = reinterpret_cast<const float4*>(P_in) + (size_t)b0 * 16;
        #pragma unroll
        for (int i = 0; i < 16; ++i) {
            int l = i * TPB + tid;
            cp16(&bP[PSLOT(l >> 4, l & 15)], &Pg[l]);
        }
        const float4* xg = reinterpret_cast<const float4*>(x_in) + (size_t)b0 * 2;
        #pragma unroll
        for (int i = 0; i < 2; ++i) {
            int l = i * TPB + tid;
            cp16(&bx[l], &xg[l]);
        }
        // z: identity staging (pitch 3) -> flat 768B bulk copy as 48 x 16B
        const float4* zg4 = reinterpret_cast<const float4*>(z_in + (size_t)b0 * 3);
        float4* bz4 = reinterpret_cast<float4*>(bz);
        if (tid < 48) cp16(&bz4[tid], &zg4[tid]);
    }
    cp_commit();

    // Q/R: broadcast tensors -> read tracklet 0's copy once (L2-resident)
    if (tid < 16) {
        reinterpret_cast<float4*>(sQu)[tid] =
            reinterpret_cast<const float4*>(Q_in)[tid];
    } else if (tid >= 32 && tid < 41) {
        sRu[tid - 32] = R_in[tid - 32];
    }

    cp_wait<0>();
    __syncthreads();

    const float dt  = 0.1f;
    const float dt2 = 0.005f;

    // ---- consume own slots into registers (swizzled, conflict-free) ----
    float P[64];
    #pragma unroll
    for (int i = 0; i < 16; ++i) {
        float4 v = bP[PSLOT(tid, i)];
        P[i * 4 + 0] = v.x; P[i * 4 + 1] = v.y;
        P[i * 4 + 2] = v.z; P[i * 4 + 3] = v.w;
    }
    float xv[8];
    {
        float4 a = bx[tid * 2 + 0], c = bx[tid * 2 + 1];
        xv[0] = a.x; xv[1] = a.y; xv[2] = a.z; xv[3] = a.w;
        xv[4] = c.x; xv[5] = c.y; xv[6] = c.z; xv[7] = c.w;
    }
    float z0 = bz[tid * 3 + 0];
    float z1 = bz[tid * 3 + 1];
    float z2 = bz[tid * 3 + 2];

    // ---- x_pred = F x ----
    const float xp0 = xv[0] + dt * xv[3] + dt2 * xv[6];
    const float xp1 = xv[1] + dt * xv[4] + dt2 * xv[7];
    const float xp2 = xv[2] + dt * xv[5];
    const float xp3 = xv[3] + dt * xv[6];
    const float xp4 = xv[4] + dt * xv[7];
    const float xp5 = xv[5];
    const float xp6 = xv[6];
    const float xp7 = xv[7];

    // ---- P <- F P ----
    #pragma unroll
    for (int j = 0; j < 8; ++j) {
        float r3 = P[3 * 8 + j], r4 = P[4 * 8 + j], r5 = P[5 * 8 + j];
        float r6 = P[6 * 8 + j], r7 = P[7 * 8 + j];
        P[0 * 8 + j] += dt * r3 + dt2 * r6;
        P[1 * 8 + j] += dt * r4 + dt2 * r7;
        P[2 * 8 + j] += dt * r5;
        P[3 * 8 + j] = r3 + dt * r6;
        P[4 * 8 + j] = r4 + dt * r7;
    }
    // ---- P <- (F P) F^T ----
    #pragma unroll
    for (int i = 0; i < 8; ++i) {
        float* row = &P[i * 8];
        float c3 = row[3], c4 = row[4], c5 = row[5], c6 = row[6], c7 = row[7];
        row[0] += dt * c3 + dt2 * c6;
        row[1] += dt * c4 + dt2 * c7;
        row[2] += dt * c5;
        row[3] = c3 + dt * c6;
        row[4] = c4 + dt * c7;
    }
    // ---- P += Q ----
    #pragma unroll
    for (int i = 0; i < 64; ++i) P[i] += sQu[i];

    // ---- S = P[0:3,0:3] + R ; adjugate inverse ----
    float S00 = P[0]  + sRu[0], S01 = P[1]  + sRu[1], S02 = P[2]  + sRu[2];
    float S10 = P[8]  + sRu[3], S11 = P[9]  + sRu[4], S12 = P[10] + sRu[5];
    float S20 = P[16] + sRu[6], S21 = P[17] + sRu[7], S22 = P[18] + sRu[8];

    float c00 = S11 * S22 - S12 * S21;
    float c01 = S12 * S20 - S10 * S22;
    float c02 = S10 * S21 - S11 * S20;
    float det = S00 * c00 + S01 * c01 + S02 * c02;
    float id  = 1.0f / det;

    float i00 = c00 * id;
    float i10 = c01 * id;
    float i20 = c02 * id;
    float i01 = (S02 * S21 - S01 * S22) * id;
    float i11 = (S00 * S22 - S02 * S20) * id;
    float i21 = (S01 * S20 - S00 * S21) * id;
    float i02 = (S01 * S12 - S02 * S11) * id;
    float i12 = (S02 * S10 - S00 * S12) * id;
    float i22 = (S00 * S11 - S01 * S10) * id;

    // ---- K = P[:,0:3] @ Sinv ----
    float K0[8], K1[8], K2[8];
    #pragma unroll
    for (int i = 0; i < 8; ++i) {
        float p0 = P[i * 8 + 0], p1 = P[i * 8 + 1], p2 = P[i * 8 + 2];
        K0[i] = p0 * i00 + p1 * i10 + p2 * i20;
        K1[i] = p0 * i01 + p1 * i11 + p2 * i21;
        K2[i] = p0 * i02 + p1 * i12 + p2 * i22;
    }

    // ---- innovation + x_upd ----
    float n0 = z0 - xp0;
    float n1 = z1 - xp1;
    float n2 = z2 - xp2;

    float xu[8];
    xu[0] = xp0 + K0[0] * n0 + K1[0] * n1 + K2[0] * n2;
    xu[1] = xp1 + K0[1] * n0 + K1[1] * n1 + K2[1] * n2;
    xu[2] = xp2 + K0[2] * n0 + K1[2] * n1 + K2[2] * n2;
    xu[3] = xp3 + K0[3] * n0 + K1[3] * n1 + K2[3] * n2;
    xu[4] = xp4 + K0[4] * n0 + K1[4] * n1 + K2[4] * n2;
    xu[5] = xp5 + K0[5] * n0 + K1[5] * n1 + K2[5] * n2;
    xu[6] = xp6 + K0[6] * n0 + K1[6] * n1 + K2[6] * n2;
    xu[7] = xp7 + K0[7] * n0 + K1[7] * n1 + K2[7] * n2;

    // ---- P_upd = P - K @ P[0:3,:]  (shadow arrays: max ILP epilogue) ----
    float HP0[8], HP1[8], HP2[8];
    #pragma unroll
    for (int j = 0; j < 8; ++j) {
        HP0[j] = P[0 * 8 + j];
        HP1[j] = P[1 * 8 + j];
        HP2[j] = P[2 * 8 + j];
    }
    #pragma unroll
    for (int i = 0; i < 8; ++i) {
        #pragma unroll
        for (int j = 0; j < 8; ++j) {
            P[i * 8 + j] -= K0[i] * HP0[j] + K1[i] * HP1[j] + K2[i] * HP2[j];
        }
    }

    // ---- stage outputs into own slots (overwrite consumed inputs) ----
    #pragma unroll
    for (int i = 0; i < 16; ++i) {
        bP[PSLOT(tid, i)] = make_float4(P[i * 4 + 0], P[i * 4 + 1],
                                        P[i * 4 + 2], P[i * 4 + 3]);
    }
    bx[tid * 2 + 0] = make_float4(xu[0], xu[1], xu[2], xu[3]);
    bx[tid * 2 + 1] = make_float4(xu[4], xu[5], xu[6], xu[7]);
    __syncthreads();

    // ---- coalesced streaming stores ----
    {
        float4* ox = reinterpret_cast<float4*>(out) + (size_t)b0 * 2;
        #pragma unroll
        for (int i = 0; i < 2; ++i) {
            int l = i * TPB + tid;
            __stcs(&ox[l], bx[l]);
        }
    }
    {
        float4* oP = reinterpret_cast<float4*>(out + (size_t)B * 8) + (size_t)b0 * 16;
        #pragma unroll
        for (int i = 0; i < 16; ++i) {
            int l = i * TPB + tid;
            __stcs(&oP[l], bP[PSLOT(l >> 4, l & 15)]);
        }
    }
}

extern "C" void kernel_launch(void* const* d_in, const int* in_sizes, int n_in,
                              void* d_out, int out_size)
{
    const float* x = (const float*)d_in[0];
    const float* P = (const float*)d_in[1];
    const float* z = (const float*)d_in[2];
    const float* Q = (const float*)d_in[3];
    const float* R = (const float*)d_in[4];
    float* out = (float*)d_out;

    const int B  = in_sizes[0] / S_DIM;        // x is [B, 8, 1]
    const int grid = B / TPB;                  // 8192 (B divisible by 64)

    static bool attr_set = false;              // idempotent host-side attribute
    if (!attr_set) {
        cudaFuncSetAttribute(ekf_kernel,
                             cudaFuncAttributeMaxDynamicSharedMemorySize, SMEM_BYTES);
        attr_set = true;
    }
    ekf_kernel<<<grid, TPB, SMEM_BYTES>>>(x, P, z, Q, R, out, B);
}